// round 12
// baseline (speedup 1.0000x reference)
#include <cuda_runtime.h>
#include <cuda_bf16.h>
#include <cstdint>
#include <cstddef>

#define DD    256
#define KK    1024
#define NVEC  32768
#define QSIZE (32*256*32*32)

#define MROWS 64
#define KCH   128
#define NCH   8
#define ASTR  264          // bf16 elements per tile row
#define XSTR  260          // fp32 rescore tile stride
#define CAP   28
#define EPS   4e-3f        // R4/R5/R7/R11-validated: zero flips

__device__ float g_enorm[KK];
__device__ __align__(16) __nv_bfloat16 g_eb[KK * DD];

// ---- smem layout (bytes); total ~109 KB -> 2 CTAs/SM ----
#define A_OFF    0
#define A_B      (MROWS * ASTR * 2)          // 33792
#define B_OFF    A_B
#define B_B      (KCH * ASTR * 2)            // 67584
#define CTRL     (A_B + B_B)                 // 101376
#define EN_OFF   (CTRL)                      // 128 f32
#define MV_OFF   (EN_OFF + 512)              // 64 u32
#define CT_OFF   (MV_OFF + 256)              // 64 i32
#define XN_OFF   (CT_OFF + 256)              // 64 f32
#define IDX_OFF  (XN_OFF + 256)              // 64 i32 (winning indices)
#define CAND_OFF (IDX_OFF + 256)             // 64*CAP i32 = 7168
#define BS_OFF   (CAND_OFF + 64*CAP*4)       // 256 f32
#define BK_OFF   (BS_OFF + 1024)             // 256 i32
#define SMEM_GEMM (BK_OFF + 1024)            // ~112 KB

__device__ __forceinline__ unsigned fenc(float f) {
    unsigned u = __float_as_uint(f);
    return (u & 0x80000000u) ? ~u : (u | 0x80000000u);
}
__device__ __forceinline__ float fdec(unsigned e) {
    return __uint_as_float((e & 0x80000000u) ? (e ^ 0x80000000u) : ~e);
}
__device__ __forceinline__ void cp16(uint32_t dst, const void* src) {
    asm volatile("cp.async.cg.shared.global [%0], [%1], 16;" :: "r"(dst), "l"(src));
}
__device__ __forceinline__ void ldsm4(uint32_t& r0, uint32_t& r1,
                                      uint32_t& r2, uint32_t& r3, uint32_t a) {
    asm volatile("ldmatrix.sync.aligned.m8n8.x4.shared.b16 {%0,%1,%2,%3}, [%4];"
                 : "=r"(r0), "=r"(r1), "=r"(r2), "=r"(r3) : "r"(a));
}
__device__ __forceinline__ void mma_bf16(float& c0, float& c1, float& c2, float& c3,
                                         uint32_t a0, uint32_t a1, uint32_t a2, uint32_t a3,
                                         uint32_t b0, uint32_t b1) {
    asm volatile("mma.sync.aligned.m16n8k16.row.col.f32.bf16.bf16.f32 "
                 "{%0,%1,%2,%3},{%4,%5,%6,%7},{%8,%9},{%0,%1,%2,%3};"
                 : "+f"(c0), "+f"(c1), "+f"(c2), "+f"(c3)
                 : "r"(a0), "r"(a1), "r"(a2), "r"(a3), "r"(b0), "r"(b1));
}

// ---------------------------------------------------------------------------
// prep: enorm + bf16 codebook; zero loss slot.
// ---------------------------------------------------------------------------
__global__ void __launch_bounds__(256)
prep_kernel(const float* __restrict__ codebook,
            float* __restrict__ d_out, int out_size) {
    int t = blockIdx.x * blockDim.x + threadIdx.x;
    int k = t >> 5, lane = t & 31;
    if (k < KK) {
        const float* p = codebook + (size_t)k * DD;
        float s = 0.0f;
        #pragma unroll
        for (int j = 0; j < DD / 32; j++) {
            float v = p[lane + j * 32];
            g_eb[(size_t)k * DD + lane + j * 32] = __float2bfloat16(v);
            s = __fadd_rn(s, __fmul_rn(v, v));
        }
        #pragma unroll
        for (int o = 16; o; o >>= 1) s += __shfl_down_sync(0xffffffffu, s, o);
        if (lane == 0) g_enorm[k] = s;
    }
    if (t == 0 && out_size > QSIZE) d_out[QSIZE] = 0.0f;
}

// ---------------------------------------------------------------------------
// Fused: bf16 mma.sync GEMM + select + exact rescore + gather/output + loss.
// 64 rows/block, 2 CTAs/SM.
// ---------------------------------------------------------------------------
__global__ void __launch_bounds__(256, 2)
gemm_select_kernel(const float* __restrict__ latent,
                   const float* __restrict__ codebook,
                   float* __restrict__ d_out, int out_size) {
    extern __shared__ __align__(1024) char sm[];
    const uint32_t smb = (uint32_t)__cvta_generic_to_shared(sm);
    __nv_bfloat16* As = (__nv_bfloat16*)(sm + A_OFF);
    float*    enorm_s = (float*)(sm + EN_OFF);
    unsigned* minval  = (unsigned*)(sm + MV_OFF);
    int*      cnt     = (int*)(sm + CT_OFF);
    float*    xn_s    = (float*)(sm + XN_OFF);
    int*      idxs    = (int*)(sm + IDX_OFF);
    int*      cand    = (int*)(sm + CAND_OFF);
    float*    bS      = (float*)(sm + BS_OFF);
    int*      bK      = (int*)(sm + BK_OFF);

    const int tid  = threadIdx.x;
    const int lane = tid & 31, wid = tid >> 5;
    const int wm   = wid >> 2, wn = wid & 3;     // 2 x 4 warp grid
    const int g    = lane >> 2, tq = lane & 3;
    const int n0   = blockIdx.x * MROWS;
    const int b    = n0 >> 10;
    const int hw0  = n0 & 1023;

    if (tid < MROWS) { minval[tid] = 0xFFFFFFFFu; cnt[tid] = 0; }

    // Stage A from latent: coalesced over hw (64 rows x 256 d).
    {
        const int hw = tid & 63, dg = tid >> 6;             // dg 0..3
        const float* latb = latent + ((size_t)b * DD + dg * 64) * 1024 + hw0 + hw;
        uint32_t* arow = (uint32_t*)(As + hw * ASTR + dg * 64);
        #pragma unroll
        for (int j = 0; j < 16; j++) {
            float v0 = latb[(size_t)(j * 4 + 0) * 1024];
            float v1 = latb[(size_t)(j * 4 + 1) * 1024];
            float v2 = latb[(size_t)(j * 4 + 2) * 1024];
            float v3 = latb[(size_t)(j * 4 + 3) * 1024];
            uint32_t p0 = ((uint32_t)__bfloat16_as_ushort(__float2bfloat16(v1)) << 16)
                        |  (uint32_t)__bfloat16_as_ushort(__float2bfloat16(v0));
            uint32_t p1 = ((uint32_t)__bfloat16_as_ushort(__float2bfloat16(v3)) << 16)
                        |  (uint32_t)__bfloat16_as_ushort(__float2bfloat16(v2));
            arow[j * 2]     = p0;
            arow[j * 2 + 1] = p1;
        }
    }

    uint32_t aAddr[2], bAddr[2];
    #pragma unroll
    for (int mi = 0; mi < 2; mi++)
        aAddr[mi] = smb + A_OFF + (uint32_t)(((wm * 32 + mi * 16 + (lane & 15)) * ASTR
                                              + (lane >> 4) * 8) * 2);
    #pragma unroll
    for (int nb = 0; nb < 2; nb++)
        bAddr[nb] = smb + B_OFF + (uint32_t)(((wn * 32 + nb * 16 + (lane & 7)
                                               + ((lane >> 4) & 1) * 8) * ASTR
                                              + ((lane >> 3) & 1) * 8) * 2);

    for (int c = 0; c < NCH; c++) {
        const int kb = c * KCH;
        __syncthreads();                         // previous chunk's B fully read
        #pragma unroll
        for (int j = 0; j < 16; j++) {
            int cc = j * 256 + tid;
            int r = cc >> 5, dc = cc & 31;
            cp16(smb + B_OFF + (uint32_t)(r * ASTR * 2 + dc * 16),
                 g_eb + (size_t)(kb + r) * DD + dc * 8);
        }
        asm volatile("cp.async.commit_group;");
        if (tid < KCH) enorm_s[tid] = g_enorm[kb + tid];
        asm volatile("cp.async.wait_group 0;");
        __syncthreads();

        float acc[2][4][4];
        #pragma unroll
        for (int mi = 0; mi < 2; mi++)
            #pragma unroll
            for (int ni = 0; ni < 4; ni++)
                #pragma unroll
                for (int jj = 0; jj < 4; jj++) acc[mi][ni][jj] = 0.0f;

        #pragma unroll
        for (int ds = 0; ds < 16; ds++) {
            uint32_t a[2][4], bfr[4][2];
            #pragma unroll
            for (int mi = 0; mi < 2; mi++)
                ldsm4(a[mi][0], a[mi][1], a[mi][2], a[mi][3], aAddr[mi] + ds * 32);
            #pragma unroll
            for (int nb = 0; nb < 2; nb++)
                ldsm4(bfr[2*nb][0], bfr[2*nb][1], bfr[2*nb+1][0], bfr[2*nb+1][1],
                      bAddr[nb] + ds * 32);
            #pragma unroll
            for (int mi = 0; mi < 2; mi++)
                #pragma unroll
                for (int ni = 0; ni < 4; ni++)
                    mma_bf16(acc[mi][ni][0], acc[mi][ni][1], acc[mi][ni][2], acc[mi][ni][3],
                             a[mi][0], a[mi][1], a[mi][2], a[mi][3],
                             bfr[ni][0], bfr[ni][1]);
        }

        #pragma unroll
        for (int mi = 0; mi < 2; mi++) {
            float m0 = 3.4e38f, m1 = 3.4e38f;
            #pragma unroll
            for (int ni = 0; ni < 4; ni++) {
                int cl = wn * 32 + ni * 8 + 2 * tq;
                float e0 = enorm_s[cl], e1 = enorm_s[cl + 1];
                acc[mi][ni][0] = e0 - 2.0f * acc[mi][ni][0];
                acc[mi][ni][1] = e1 - 2.0f * acc[mi][ni][1];
                acc[mi][ni][2] = e0 - 2.0f * acc[mi][ni][2];
                acc[mi][ni][3] = e1 - 2.0f * acc[mi][ni][3];
                m0 = fminf(m0, fminf(acc[mi][ni][0], acc[mi][ni][1]));
                m1 = fminf(m1, fminf(acc[mi][ni][2], acc[mi][ni][3]));
            }
            m0 = fminf(m0, __shfl_xor_sync(0xffffffffu, m0, 1));
            m0 = fminf(m0, __shfl_xor_sync(0xffffffffu, m0, 2));
            m1 = fminf(m1, __shfl_xor_sync(0xffffffffu, m1, 1));
            m1 = fminf(m1, __shfl_xor_sync(0xffffffffu, m1, 2));
            if (tq == 0) {
                atomicMin(&minval[wm * 32 + mi * 16 + g],     fenc(m0));
                atomicMin(&minval[wm * 32 + mi * 16 + g + 8], fenc(m1));
            }
        }
        __syncthreads();

        #pragma unroll
        for (int mi = 0; mi < 2; mi++) {
            int rl0 = wm * 32 + mi * 16 + g, rl1 = rl0 + 8;
            float t0 = fdec(minval[rl0]) + EPS;
            float t1 = fdec(minval[rl1]) + EPS;
            #pragma unroll
            for (int ni = 0; ni < 4; ni++) {
                int k0 = kb + wn * 32 + ni * 8 + 2 * tq;
                if (acc[mi][ni][0] <= t0) { int p = atomicAdd(&cnt[rl0], 1); if (p < CAP) cand[rl0 * CAP + p] = k0; }
                if (acc[mi][ni][1] <= t0) { int p = atomicAdd(&cnt[rl0], 1); if (p < CAP) cand[rl0 * CAP + p] = k0 + 1; }
                if (acc[mi][ni][2] <= t1) { int p = atomicAdd(&cnt[rl1], 1); if (p < CAP) cand[rl1 * CAP + p] = k0; }
                if (acc[mi][ni][3] <= t1) { int p = atomicAdd(&cnt[rl1], 1); if (p < CAP) cand[rl1 * CAP + p] = k0 + 1; }
            }
        }
    }
    __syncthreads();

    // ---- exact rescore: reload fp32 x over dead A/B tiles ----
    float* xrs = (float*)sm;                     // [64][XSTR] = 66560 B
    {
        const int hw = tid & 63, dg = tid >> 6;
        const float* latb = latent + ((size_t)b * DD + dg * 64) * 1024 + hw0 + hw;
        float* xrow = xrs + hw * XSTR + dg * 64;
        #pragma unroll 8
        for (int j = 0; j < 64; j++)
            xrow[j] = latb[(size_t)j * 1024];
    }
    __syncthreads();
    if (tid < MROWS) {
        const float4* xr = (const float4*)(xrs + tid * XSTR);
        float sum = 0.0f;
        #pragma unroll 8
        for (int i = 0; i < DD / 4; i++) {
            float4 v = xr[i];
            sum = __fadd_rn(sum, __fmul_rn(v.x, v.x));
            sum = __fadd_rn(sum, __fmul_rn(v.y, v.y));
            sum = __fadd_rn(sum, __fmul_rn(v.z, v.z));
            sum = __fadd_rn(sum, __fmul_rn(v.w, v.w));
        }
        xn_s[tid] = sum;
    }
    __syncthreads();
    {
        int r = tid >> 2, c0 = tid & 3;          // 4 threads per row
        int cnr = cnt[r];
        float xn = xn_s[r];
        const float4* xp = (const float4*)(xrs + r * XSTR);
        float bs = 3.4e38f; int bi = 0x7fffffff;
        if (cnr <= CAP) {
            for (int cc = c0; cc < cnr; cc += 4) {
                int k = cand[r * CAP + cc];
                const float4* ep = (const float4*)(codebook + (size_t)k * DD);
                float a = 0.0f;
                #pragma unroll 8
                for (int i = 0; i < DD / 4; i++) {
                    float4 xv = xp[i], ev = ep[i];
                    a = fmaf(xv.x, ev.x, a); a = fmaf(xv.y, ev.y, a);
                    a = fmaf(xv.z, ev.z, a); a = fmaf(xv.w, ev.w, a);
                }
                float sc = __fsub_rn(__fadd_rn(xn, g_enorm[k]), __fmul_rn(2.0f, a));
                if (sc < bs || (sc == bs && k < bi)) { bs = sc; bi = k; }
            }
        } else {
            // hard backstop: exact scan (expected: never taken)
            for (int k = c0; k < KK; k += 4) {
                const float4* ep = (const float4*)(codebook + (size_t)k * DD);
                float a = 0.0f;
                #pragma unroll 8
                for (int i = 0; i < DD / 4; i++) {
                    float4 xv = xp[i], ev = ep[i];
                    a = fmaf(xv.x, ev.x, a); a = fmaf(xv.y, ev.y, a);
                    a = fmaf(xv.z, ev.z, a); a = fmaf(xv.w, ev.w, a);
                }
                float sc = __fsub_rn(__fadd_rn(xn, g_enorm[k]), __fmul_rn(2.0f, a));
                if (sc < bs || (sc == bs && k < bi)) { bs = sc; bi = k; }
            }
        }
        bS[c0 * 64 + r] = bs;
        bK[c0 * 64 + r] = bi;
    }
    __syncthreads();
    if (tid < MROWS) {
        float bs = bS[tid]; int bi = bK[tid];
        #pragma unroll
        for (int cc = 1; cc < 4; cc++) {
            float s = bS[cc * 64 + tid]; int k = bK[cc * 64 + tid];
            if (s < bs || (s == bs && k < bi)) { bs = s; bi = k; }
        }
        idxs[tid] = bi;
    }
    __syncthreads();

    // ---- fused gather + output + loss: x is already in smem ----
    {
        const int hw = tid & 63, dg = tid >> 6;
        const int kidx = idxs[hw];
        const float4* qrow  = (const float4*)(codebook + (size_t)kidx * DD + dg * 64);
        const float4* xrow4 = (const float4*)(xrs + hw * XSTR + dg * 64);
        float* outb = d_out + ((size_t)b * DD + dg * 64) * 1024 + hw0 + hw;
        float lsum = 0.0f;
        #pragma unroll
        for (int jq = 0; jq < 16; jq++) {
            float4 xv = xrow4[jq];
            float4 qv = __ldg(qrow + jq);
            float d0 = __fsub_rn(qv.x, xv.x);
            float d1 = __fsub_rn(qv.y, xv.y);
            float d2 = __fsub_rn(qv.z, xv.z);
            float d3 = __fsub_rn(qv.w, xv.w);
            outb[(size_t)(jq * 4 + 0) * 1024] = __fadd_rn(xv.x, d0);
            outb[(size_t)(jq * 4 + 1) * 1024] = __fadd_rn(xv.y, d1);
            outb[(size_t)(jq * 4 + 2) * 1024] = __fadd_rn(xv.z, d2);
            outb[(size_t)(jq * 4 + 3) * 1024] = __fadd_rn(xv.w, d3);
            lsum += d0 * d0 + d1 * d1 + d2 * d2 + d3 * d3;
        }
        // block-reduce loss (reuse cand area)
        float* red = (float*)cand;
        red[tid] = lsum;
        __syncthreads();
        #pragma unroll
        for (int s = 128; s > 0; s >>= 1) {
            if (tid < s) red[tid] += red[tid + s];
            __syncthreads();
        }
        if (tid == 0 && out_size > QSIZE)
            atomicAdd(d_out + QSIZE, 1.25f * red[0] * (1.0f / (float)QSIZE));
    }
}

extern "C" void kernel_launch(void* const* d_in, const int* in_sizes, int n_in,
                              void* d_out, int out_size) {
    const float* latent   = (const float*)d_in[0];
    const float* codebook = (const float*)d_in[1];
    float* out = (float*)d_out;

    cudaFuncSetAttribute(gemm_select_kernel,
                         cudaFuncAttributeMaxDynamicSharedMemorySize, SMEM_GEMM);

    prep_kernel<<<KK * 32 / 256, 256>>>(codebook, out, out_size);
    gemm_select_kernel<<<NVEC / MROWS, 256, SMEM_GEMM>>>(latent, codebook, out, out_size);
}

// round 13
// speedup vs baseline: 1.0583x; 1.0583x over previous
#include <cuda_runtime.h>
#include <cuda_bf16.h>
#include <cstdint>
#include <cstddef>

#define DD    256
#define KK    1024
#define NVEC  32768
#define QSIZE (32*256*32*32)

#define MROWS 64
#define KCH   128
#define NCH   8
#define ASTR  264          // A tile: bf16 elements per row (padded)
#define BROW  512          // B tile: bytes per code row (linear, swizzled content)
#define XSTR  260          // fp32 rescore tile stride
#define CAP   28
#define EPS   4e-3f        // R4/R5/R7/R11/R12-validated: zero flips

__device__ float g_enorm[KK];
__device__ __align__(16) __nv_bfloat16 g_eb[KK * DD];   // PRE-SWIZZLED rows

// ---- smem layout (bytes); ~110 KB -> 2 CTAs/SM ----
#define A_OFF    0
#define A_B      (MROWS * ASTR * 2)          // 33792
#define B_OFF    A_B                          // 1024-aligned (33*1024)
#define B_B      (KCH * BROW)                // 65536
#define CTRL     (A_B + B_B)                 // 99328
#define EN_OFF   (CTRL)                      // 128 f32
#define MV_OFF   (EN_OFF + 512)              // 64 u32
#define CT_OFF   (MV_OFF + 256)              // 64 i32
#define XN_OFF   (CT_OFF + 256)              // 64 f32
#define IDX_OFF  (XN_OFF + 256)              // 64 i32
#define MB_OFF   (IDX_OFF + 256)             // mbarrier (16 B slot)
#define CAND_OFF (MB_OFF + 16)               // 64*CAP i32 = 7168
#define BS_OFF   (CAND_OFF + 64*CAP*4)       // 256 f32
#define BK_OFF   (BS_OFF + 1024)             // 256 i32
#define SMEM_GEMM (BK_OFF + 1024)            // 110096 B

__device__ __forceinline__ unsigned fenc(float f) {
    unsigned u = __float_as_uint(f);
    return (u & 0x80000000u) ? ~u : (u | 0x80000000u);
}
__device__ __forceinline__ float fdec(unsigned e) {
    return __uint_as_float((e & 0x80000000u) ? (e ^ 0x80000000u) : ~e);
}
__device__ __forceinline__ void bulk_cp(uint32_t dst, const void* src,
                                        uint32_t bytes, uint32_t mbar) {
    asm volatile(
        "cp.async.bulk.shared::cluster.global.mbarrier::complete_tx::bytes "
        "[%0], [%1], %2, [%3];"
        :: "r"(dst), "l"(src), "r"(bytes), "r"(mbar) : "memory");
}
__device__ __forceinline__ void mbar_wait(uint32_t mbar, unsigned parity) {
    asm volatile(
        "{\n\t.reg .pred P1;\n\t"
        "WL_%=:\n\t"
        "mbarrier.try_wait.parity.acquire.cta.shared::cta.b64 P1, [%0], %1, 0x989680;\n\t"
        "@P1 bra.uni WD_%=;\n\t"
        "bra.uni WL_%=;\n\t"
        "WD_%=:\n\t}"
        :: "r"(mbar), "r"(parity) : "memory");
}
__device__ __forceinline__ void ldsm4(uint32_t& r0, uint32_t& r1,
                                      uint32_t& r2, uint32_t& r3, uint32_t a) {
    asm volatile("ldmatrix.sync.aligned.m8n8.x4.shared.b16 {%0,%1,%2,%3}, [%4];"
                 : "=r"(r0), "=r"(r1), "=r"(r2), "=r"(r3) : "r"(a));
}
__device__ __forceinline__ void mma_bf16(float& c0, float& c1, float& c2, float& c3,
                                         uint32_t a0, uint32_t a1, uint32_t a2, uint32_t a3,
                                         uint32_t b0, uint32_t b1) {
    asm volatile("mma.sync.aligned.m16n8k16.row.col.f32.bf16.bf16.f32 "
                 "{%0,%1,%2,%3},{%4,%5,%6,%7},{%8,%9},{%0,%1,%2,%3};"
                 : "+f"(c0), "+f"(c1), "+f"(c2), "+f"(c3)
                 : "r"(a0), "r"(a1), "r"(a2), "r"(a3), "r"(b0), "r"(b1));
}

// ---------------------------------------------------------------------------
// prep: enorm + PRE-SWIZZLED bf16 codebook (d' = d ^ ((k&7)<<3)); zero loss.
// ---------------------------------------------------------------------------
__global__ void __launch_bounds__(256)
prep_kernel(const float* __restrict__ codebook,
            float* __restrict__ d_out, int out_size) {
    int t = blockIdx.x * blockDim.x + threadIdx.x;
    int k = t >> 5, lane = t & 31;
    if (k < KK) {
        const float* p = codebook + (size_t)k * DD;
        const int sw = (k & 7) << 3;
        float s = 0.0f;
        #pragma unroll
        for (int j = 0; j < DD / 32; j++) {
            int d = lane + j * 32;
            float v = p[d];
            g_eb[(size_t)k * DD + (d ^ sw)] = __float2bfloat16(v);
            s = __fadd_rn(s, __fmul_rn(v, v));
        }
        #pragma unroll
        for (int o = 16; o; o >>= 1) s += __shfl_down_sync(0xffffffffu, s, o);
        if (lane == 0) g_enorm[k] = s;
    }
    if (t == 0 && out_size > QSIZE) d_out[QSIZE] = 0.0f;
}

// ---------------------------------------------------------------------------
// Fused GEMM (bulk-copied B) + select + exact rescore + gather/output + loss.
// ---------------------------------------------------------------------------
__global__ void __launch_bounds__(256, 2)
gemm_select_kernel(const float* __restrict__ latent,
                   const float* __restrict__ codebook,
                   float* __restrict__ d_out, int out_size) {
    extern __shared__ __align__(1024) char sm[];
    const uint32_t smb = (uint32_t)__cvta_generic_to_shared(sm);
    __nv_bfloat16* As = (__nv_bfloat16*)(sm + A_OFF);
    float*    enorm_s = (float*)(sm + EN_OFF);
    unsigned* minval  = (unsigned*)(sm + MV_OFF);
    int*      cnt     = (int*)(sm + CT_OFF);
    float*    xn_s    = (float*)(sm + XN_OFF);
    int*      idxs    = (int*)(sm + IDX_OFF);
    int*      cand    = (int*)(sm + CAND_OFF);
    float*    bS      = (float*)(sm + BS_OFF);
    int*      bK      = (int*)(sm + BK_OFF);
    const uint32_t mbar = smb + MB_OFF;

    const int tid  = threadIdx.x;
    const int lane = tid & 31, wid = tid >> 5;
    const int wm   = wid >> 2, wn = wid & 3;     // 2 x 4 warp grid
    const int g    = lane >> 2, tq = lane & 3;
    const int n0   = blockIdx.x * MROWS;
    const int b    = n0 >> 10;
    const int hw0  = n0 & 1023;

    if (tid == 0)
        asm volatile("mbarrier.init.shared.b64 [%0], 1;" :: "r"(mbar) : "memory");
    if (tid < MROWS) { minval[tid] = 0xFFFFFFFFu; cnt[tid] = 0; }

    // Stage A from latent: coalesced over hw (64 rows x 256 d), padded layout.
    {
        const int hw = tid & 63, dg = tid >> 6;
        const float* latb = latent + ((size_t)b * DD + dg * 64) * 1024 + hw0 + hw;
        uint32_t* arow = (uint32_t*)(As + hw * ASTR + dg * 64);
        #pragma unroll
        for (int j = 0; j < 16; j++) {
            float v0 = latb[(size_t)(j * 4 + 0) * 1024];
            float v1 = latb[(size_t)(j * 4 + 1) * 1024];
            float v2 = latb[(size_t)(j * 4 + 2) * 1024];
            float v3 = latb[(size_t)(j * 4 + 3) * 1024];
            uint32_t p0 = ((uint32_t)__bfloat16_as_ushort(__float2bfloat16(v1)) << 16)
                        |  (uint32_t)__bfloat16_as_ushort(__float2bfloat16(v0));
            uint32_t p1 = ((uint32_t)__bfloat16_as_ushort(__float2bfloat16(v3)) << 16)
                        |  (uint32_t)__bfloat16_as_ushort(__float2bfloat16(v2));
            arow[j * 2]     = p0;
            arow[j * 2 + 1] = p1;
        }
    }

    uint32_t aAddr[2];
    #pragma unroll
    for (int mi = 0; mi < 2; mi++)
        aAddr[mi] = smb + A_OFF + (uint32_t)(((wm * 32 + mi * 16 + (lane & 15)) * ASTR
                                              + (lane >> 4) * 8) * 2);
    // B: linear 512B rows, swizzled content. Per-lane row + chunk-xor params.
    uint32_t bBase[2]; uint32_t rx[2];
    const uint32_t hs = (lane >> 3) & 1;
    #pragma unroll
    for (int nb = 0; nb < 2; nb++) {
        uint32_t r = wn * 32 + nb * 16 + (lane & 7) + ((lane >> 4) & 1) * 8;
        bBase[nb] = smb + B_OFF + r * BROW;
        rx[nb] = r & 7;
    }

    for (int c = 0; c < NCH; c++) {
        const int kb = c * KCH;
        __syncthreads();                         // prev chunk's B fully read; init visible
        if (tid == 0) {
            asm volatile("mbarrier.arrive.expect_tx.shared.b64 _, [%0], %1;"
                         :: "r"(mbar), "r"((uint32_t)B_B) : "memory");
            bulk_cp(smb + B_OFF, g_eb + (size_t)kb * DD, B_B, mbar);
        }
        if (tid < KCH) enorm_s[tid] = g_enorm[kb + tid];
        mbar_wait(mbar, c & 1);
        __syncthreads();                         // enorm_s visible to all

        float acc[2][4][4];
        #pragma unroll
        for (int mi = 0; mi < 2; mi++)
            #pragma unroll
            for (int ni = 0; ni < 4; ni++)
                #pragma unroll
                for (int jj = 0; jj < 4; jj++) acc[mi][ni][jj] = 0.0f;

        #pragma unroll
        for (int ds = 0; ds < 16; ds++) {
            uint32_t a[2][4], bfr[4][2];
            #pragma unroll
            for (int mi = 0; mi < 2; mi++)
                ldsm4(a[mi][0], a[mi][1], a[mi][2], a[mi][3], aAddr[mi] + ds * 32);
            #pragma unroll
            for (int nb = 0; nb < 2; nb++) {
                uint32_t baddr = bBase[nb] + ((((uint32_t)(ds << 1) | hs) ^ rx[nb]) << 4);
                ldsm4(bfr[2*nb][0], bfr[2*nb][1], bfr[2*nb+1][0], bfr[2*nb+1][1], baddr);
            }
            #pragma unroll
            for (int mi = 0; mi < 2; mi++)
                #pragma unroll
                for (int ni = 0; ni < 4; ni++)
                    mma_bf16(acc[mi][ni][0], acc[mi][ni][1], acc[mi][ni][2], acc[mi][ni][3],
                             a[mi][0], a[mi][1], a[mi][2], a[mi][3],
                             bfr[ni][0], bfr[ni][1]);
        }

        #pragma unroll
        for (int mi = 0; mi < 2; mi++) {
            float m0 = 3.4e38f, m1 = 3.4e38f;
            #pragma unroll
            for (int ni = 0; ni < 4; ni++) {
                int cl = wn * 32 + ni * 8 + 2 * tq;
                float e0 = enorm_s[cl], e1 = enorm_s[cl + 1];
                acc[mi][ni][0] = e0 - 2.0f * acc[mi][ni][0];
                acc[mi][ni][1] = e1 - 2.0f * acc[mi][ni][1];
                acc[mi][ni][2] = e0 - 2.0f * acc[mi][ni][2];
                acc[mi][ni][3] = e1 - 2.0f * acc[mi][ni][3];
                m0 = fminf(m0, fminf(acc[mi][ni][0], acc[mi][ni][1]));
                m1 = fminf(m1, fminf(acc[mi][ni][2], acc[mi][ni][3]));
            }
            m0 = fminf(m0, __shfl_xor_sync(0xffffffffu, m0, 1));
            m0 = fminf(m0, __shfl_xor_sync(0xffffffffu, m0, 2));
            m1 = fminf(m1, __shfl_xor_sync(0xffffffffu, m1, 1));
            m1 = fminf(m1, __shfl_xor_sync(0xffffffffu, m1, 2));
            if (tq == 0) {
                atomicMin(&minval[wm * 32 + mi * 16 + g],     fenc(m0));
                atomicMin(&minval[wm * 32 + mi * 16 + g + 8], fenc(m1));
            }
        }
        __syncthreads();

        #pragma unroll
        for (int mi = 0; mi < 2; mi++) {
            int rl0 = wm * 32 + mi * 16 + g, rl1 = rl0 + 8;
            float t0 = fdec(minval[rl0]) + EPS;
            float t1 = fdec(minval[rl1]) + EPS;
            #pragma unroll
            for (int ni = 0; ni < 4; ni++) {
                int k0 = kb + wn * 32 + ni * 8 + 2 * tq;
                if (acc[mi][ni][0] <= t0) { int p = atomicAdd(&cnt[rl0], 1); if (p < CAP) cand[rl0 * CAP + p] = k0; }
                if (acc[mi][ni][1] <= t0) { int p = atomicAdd(&cnt[rl0], 1); if (p < CAP) cand[rl0 * CAP + p] = k0 + 1; }
                if (acc[mi][ni][2] <= t1) { int p = atomicAdd(&cnt[rl1], 1); if (p < CAP) cand[rl1 * CAP + p] = k0; }
                if (acc[mi][ni][3] <= t1) { int p = atomicAdd(&cnt[rl1], 1); if (p < CAP) cand[rl1 * CAP + p] = k0 + 1; }
            }
        }
    }
    __syncthreads();

    // ---- exact rescore: reload fp32 x over dead A/B tiles ----
    float* xrs = (float*)sm;                     // [64][XSTR] = 66560 B
    {
        const int hw = tid & 63, dg = tid >> 6;
        const float* latb = latent + ((size_t)b * DD + dg * 64) * 1024 + hw0 + hw;
        float* xrow = xrs + hw * XSTR + dg * 64;
        #pragma unroll 8
        for (int j = 0; j < 64; j++)
            xrow[j] = latb[(size_t)j * 1024];
    }
    __syncthreads();
    if (tid < MROWS) {
        const float4* xr = (const float4*)(xrs + tid * XSTR);
        float sum = 0.0f;
        #pragma unroll 8
        for (int i = 0; i < DD / 4; i++) {
            float4 v = xr[i];
            sum = __fadd_rn(sum, __fmul_rn(v.x, v.x));
            sum = __fadd_rn(sum, __fmul_rn(v.y, v.y));
            sum = __fadd_rn(sum, __fmul_rn(v.z, v.z));
            sum = __fadd_rn(sum, __fmul_rn(v.w, v.w));
        }
        xn_s[tid] = sum;
    }
    __syncthreads();
    {
        int r = tid >> 2, c0 = tid & 3;
        int cnr = cnt[r];
        float xn = xn_s[r];
        const float4* xp = (const float4*)(xrs + r * XSTR);
        float bs = 3.4e38f; int bi = 0x7fffffff;
        if (cnr <= CAP) {
            for (int cc = c0; cc < cnr; cc += 4) {
                int k = cand[r * CAP + cc];
                const float4* ep = (const float4*)(codebook + (size_t)k * DD);
                float a = 0.0f;
                #pragma unroll 8
                for (int i = 0; i < DD / 4; i++) {
                    float4 xv = xp[i], ev = ep[i];
                    a = fmaf(xv.x, ev.x, a); a = fmaf(xv.y, ev.y, a);
                    a = fmaf(xv.z, ev.z, a); a = fmaf(xv.w, ev.w, a);
                }
                float sc = __fsub_rn(__fadd_rn(xn, g_enorm[k]), __fmul_rn(2.0f, a));
                if (sc < bs || (sc == bs && k < bi)) { bs = sc; bi = k; }
            }
        } else {
            for (int k = c0; k < KK; k += 4) {   // backstop: exact scan
                const float4* ep = (const float4*)(codebook + (size_t)k * DD);
                float a = 0.0f;
                #pragma unroll 8
                for (int i = 0; i < DD / 4; i++) {
                    float4 xv = xp[i], ev = ep[i];
                    a = fmaf(xv.x, ev.x, a); a = fmaf(xv.y, ev.y, a);
                    a = fmaf(xv.z, ev.z, a); a = fmaf(xv.w, ev.w, a);
                }
                float sc = __fsub_rn(__fadd_rn(xn, g_enorm[k]), __fmul_rn(2.0f, a));
                if (sc < bs || (sc == bs && k < bi)) { bs = sc; bi = k; }
            }
        }
        bS[c0 * 64 + r] = bs;
        bK[c0 * 64 + r] = bi;
    }
    __syncthreads();
    if (tid < MROWS) {
        float bs = bS[tid]; int bi = bK[tid];
        #pragma unroll
        for (int cc = 1; cc < 4; cc++) {
            float s = bS[cc * 64 + tid]; int k = bK[cc * 64 + tid];
            if (s < bs || (s == bs && k < bi)) { bs = s; bi = k; }
        }
        idxs[tid] = bi;
    }
    __syncthreads();

    // ---- fused gather + output + loss ----
    {
        const int hw = tid & 63, dg = tid >> 6;
        const int kidx = idxs[hw];
        const float4* qrow  = (const float4*)(codebook + (size_t)kidx * DD + dg * 64);
        const float4* xrow4 = (const float4*)(xrs + hw * XSTR + dg * 64);
        float* outb = d_out + ((size_t)b * DD + dg * 64) * 1024 + hw0 + hw;
        float lsum = 0.0f;
        #pragma unroll
        for (int jq = 0; jq < 16; jq++) {
            float4 xv = xrow4[jq];
            float4 qv = __ldg(qrow + jq);
            float d0 = __fsub_rn(qv.x, xv.x);
            float d1 = __fsub_rn(qv.y, xv.y);
            float d2 = __fsub_rn(qv.z, xv.z);
            float d3 = __fsub_rn(qv.w, xv.w);
            outb[(size_t)(jq * 4 + 0) * 1024] = __fadd_rn(xv.x, d0);
            outb[(size_t)(jq * 4 + 1) * 1024] = __fadd_rn(xv.y, d1);
            outb[(size_t)(jq * 4 + 2) * 1024] = __fadd_rn(xv.z, d2);
            outb[(size_t)(jq * 4 + 3) * 1024] = __fadd_rn(xv.w, d3);
            lsum += d0 * d0 + d1 * d1 + d2 * d2 + d3 * d3;
        }
        float* red = (float*)cand;
        red[tid] = lsum;
        __syncthreads();
        #pragma unroll
        for (int s = 128; s > 0; s >>= 1) {
            if (tid < s) red[tid] += red[tid + s];
            __syncthreads();
        }
        if (tid == 0 && out_size > QSIZE)
            atomicAdd(d_out + QSIZE, 1.25f * red[0] * (1.0f / (float)QSIZE));
    }
}

extern "C" void kernel_launch(void* const* d_in, const int* in_sizes, int n_in,
                              void* d_out, int out_size) {
    const float* latent   = (const float*)d_in[0];
    const float* codebook = (const float*)d_in[1];
    float* out = (float*)d_out;

    cudaFuncSetAttribute(gemm_select_kernel,
                         cudaFuncAttributeMaxDynamicSharedMemorySize, SMEM_GEMM);

    prep_kernel<<<KK * 32 / 256, 256>>>(codebook, out, out_size);
    gemm_select_kernel<<<NVEC / MROWS, 256, SMEM_GEMM>>>(latent, codebook, out, out_size);
}